// round 12
// baseline (speedup 1.0000x reference)
#include <cuda_runtime.h>
#include <cuda_bf16.h>
#include <cuda_fp16.h>
#include <cstdint>

// Problem constants
#define NC    188
#define PF    16
#define HID   128
#define H2    64
#define DE    5
#define DOUT  6
#define NT    5
#define BATCH 32
#define TPB   384   // 12 warps; one m16 tile per warp (192 rows)
#define RPB   4     // receivers per block (DS/B staged once; 47*4 = 188)

// DS tile in smem: 192 rows x 136 halves (272 B = 17 uint4 = 68 u32 stride)
#define SROW_U32 68
#define SROW_U4  17
#define DS_BYTES 52224      // 192 * 272
#define B_BYTES  17408      // 64 * 272
#define SM_B     52224
#define DYN_SMEM 69632      // 3 blocks/SM (dynamic); static ~3.9KB -> 221KB/SM

// Scratch
__device__ float g_O[BATCH * NC * DOUT];
__device__ __align__(16) __half g_DRh[BATCH * NC * HID];  // fp16 DR
__device__ __align__(16) __half g_DSh[BATCH * NC * HID];  // fp16 DS
__device__ __align__(16) __half g_W2h[H2 * 136];
__device__ float g_P1[BATCH * 16 * HID];   // fc1 split-K partials

__device__ __forceinline__ void mma_f16(float* d, const uint32_t* a,
                                        uint32_t b0, uint32_t b1) {
    asm volatile(
        "mma.sync.aligned.m16n8k16.row.col.f32.f16.f16.f32 "
        "{%0,%1,%2,%3}, {%4,%5,%6,%7}, {%8,%9}, {%0,%1,%2,%3};"
        : "+f"(d[0]), "+f"(d[1]), "+f"(d[2]), "+f"(d[3])
        : "r"(a[0]), "r"(a[1]), "r"(a[2]), "r"(a[3]), "r"(b0), "r"(b1));
}

// relu(a + b) on packed f16x2
__device__ __forceinline__ uint32_t h2_relu_add(uint32_t a, uint32_t b) {
    uint32_t r;
    asm("{\n\tadd.f16x2 %0, %1, %2;\n\tmax.f16x2 %0, %0, %3;\n\t}"
        : "=r"(r) : "r"(a), "r"(b), "r"(0u));
    return r;
}

// ============================================================================
// Kernel P: per-node layer-1 half-dots -> fp16. 4 nodes/block, 512 threads.
// ============================================================================
__global__ void __launch_bounds__(512) precompute_kernel(
    const float* __restrict__ x,
    const float* __restrict__ fr1_w, const float* __restrict__ fr1_b)
{
    __shared__ float SX[4][PF];
    const int sub = threadIdx.x >> 7;
    const int i = threadIdx.x & (HID - 1);
    const int n = blockIdx.x * 4 + sub;          // 47*4 = 188
    const int b = blockIdx.y;
    if (i < PF) SX[sub][i] = x[((size_t)b * NC + n) * PF + i];
    __syncthreads();
    float dr = fr1_b[i], ds = 0.f;
    #pragma unroll
    for (int m = 0; m < PF; m++) {
        float xm = SX[sub][m];
        dr = fmaf(xm, fr1_w[m * HID + i], dr);
        ds = fmaf(xm, fr1_w[(PF + m) * HID + i], ds);
    }
    g_DRh[((size_t)b * NC + n) * HID + i] = __float2half_rn(dr);
    g_DSh[((size_t)b * NC + n) * HID + i] = __float2half_rn(ds);
}

// ============================================================================
// Kernel W: W2^T as fp16 image [64][136]
// ============================================================================
__global__ void __launch_bounds__(256) w2prep_kernel(const float* __restrict__ fr2_w)
{
    int idx = blockIdx.x * 256 + threadIdx.x;
    if (idx < HID * H2) {
        int o = idx >> 7, k = idx & 127;
        g_W2h[o * 136 + k] = __float2half_rn(fr2_w[k * H2 + o]);
    }
}

// ============================================================================
// Kernel A: one block per (4 receivers, batch). fp16 mma.sync GEMM for 4
// receivers + fused object MLP tail (DS smem region reused for SH1/SH2).
// ============================================================================
__global__ void __launch_bounds__(TPB, 3) edge_obj_kernel(
    const float* __restrict__ x,
    const float* __restrict__ fr2_b,
    const float* __restrict__ fr3_w, const float* __restrict__ fr3_b,
    const float* __restrict__ fo1_w, const float* __restrict__ fo1_b,
    const float* __restrict__ fo2_w, const float* __restrict__ fo2_b,
    const float* __restrict__ fo3_w, const float* __restrict__ fo3_b)
{
    extern __shared__ __align__(16) unsigned char dsm[];
    __shared__ __align__(16) float SW3p[H2 * 8];   // per o: w3[0..4], b2, 0, 0
    __shared__ __align__(8) uint32_t SDR16[RPB][64];
    __shared__ float SC[RPB][24];                  // [x(16), Ebar(5)]
    __shared__ float SB3[8];
    __shared__ float SRED[12 * DE];

    const uint32_t* DS32 = reinterpret_cast<const uint32_t*>(dsm);
    const uint32_t* B32 = reinterpret_cast<const uint32_t*>(dsm + SM_B);

    const int rbase = blockIdx.x * RPB, b = blockIdx.y;
    const int tid = threadIdx.x, wid = tid >> 5, lane = tid & 31;
    const int gid = lane >> 2, tig = lane & 3;

    // ---- stage: DS tile (raw copy), B, DR x RPB, W3, x ----
    {
        const uint4* src = reinterpret_cast<const uint4*>(
            g_DSh + (size_t)b * NC * HID);
        uint4* dst = reinterpret_cast<uint4*>(dsm);
        #pragma unroll 4
        for (int idx = tid; idx < NC * 16; idx += TPB) {   // 3008 uint4
            int row = idx >> 4, col = idx & 15;
            dst[row * SROW_U4 + col] = src[idx];
        }
        if (tid < 68) {   // pad rows 188..191 = -inf so relu -> 0
            uint4 ninf = {0xFC00FC00u, 0xFC00FC00u, 0xFC00FC00u, 0xFC00FC00u};
            int row = NC + tid / SROW_U4, col = tid % SROW_U4;
            dst[row * SROW_U4 + col] = ninf;
        }
    }
    {
        const uint4* sh = reinterpret_cast<const uint4*>(g_W2h);
        uint4* dh = reinterpret_cast<uint4*>(dsm + SM_B);
        #pragma unroll 2
        for (int idx = tid; idx < B_BYTES / 16; idx += TPB) dh[idx] = sh[idx];
    }
    if (tid < RPB * 64) {
        int rr = tid >> 6, w = tid & 63;
        SDR16[rr][w] = reinterpret_cast<const uint32_t*>(
            g_DRh + ((size_t)b * NC + rbase + rr) * HID)[w];
    }
    for (int idx = tid; idx < H2 * 8; idx += TPB) {
        int o = idx >> 3, k = idx & 7;
        SW3p[idx] = (k < 5) ? fr3_w[o * DE + k] : (k == 5 ? fr2_b[o] : 0.f);
    }
    if (tid < DE) SB3[tid] = fr3_b[tid];
    if (tid >= 32 && tid < 32 + RPB * PF) {
        int t = tid - 32, sub = t >> 4, m = t & 15;
        SC[sub][m] = x[((size_t)b * NC + rbase + sub) * PF + m];
    }
    __syncthreads();

    const int abase0 = (wid * 16 + gid) * SROW_U32;
    const int row0 = wid * 16 + gid, row1 = row0 + 8;

    #pragma unroll 1
    for (int rr = 0; rr < RPB; rr++) {
        const int r = rbase + rr;

        // ---- GEMM: warp wid owns m16 tile rows [16*wid, 16*wid+16) ----
        float d[8][4];
        #pragma unroll
        for (int nt = 0; nt < 8; nt++)
            #pragma unroll
            for (int e = 0; e < 4; e++) d[nt][e] = 0.f;

        #pragma unroll
        for (int kt = 0; kt < 8; kt++) {
            const int kb = kt * 8 + tig;
            const uint32_t dr0 = SDR16[rr][kb], dr1 = SDR16[rr][kb + 4];
            uint32_t af[4];
            af[0] = h2_relu_add(DS32[abase0 + kb], dr0);
            af[1] = h2_relu_add(DS32[abase0 + 8 * SROW_U32 + kb], dr0);
            af[2] = h2_relu_add(DS32[abase0 + kb + 4], dr1);
            af[3] = h2_relu_add(DS32[abase0 + 8 * SROW_U32 + kb + 4], dr1);
            #pragma unroll
            for (int nt = 0; nt < 8; nt++) {
                const int bi = (nt * 8 + gid) * SROW_U32 + kb;
                mma_f16(d[nt], af, B32[bi], B32[bi + 4]);
            }
        }

        // ---- fragment-direct epilogue: layer 3 partials ----
        float p0[DE] = {0.f, 0.f, 0.f, 0.f, 0.f};
        float p1[DE] = {0.f, 0.f, 0.f, 0.f, 0.f};
        #pragma unroll
        for (int nt = 0; nt < 8; nt++) {
            const int c = nt * 8 + tig * 2;
            float4 wA0 = *reinterpret_cast<const float4*>(SW3p + c * 8);
            float4 wB0 = *reinterpret_cast<const float4*>(SW3p + c * 8 + 4);
            float4 wA1 = *reinterpret_cast<const float4*>(SW3p + (c + 1) * 8);
            float4 wB1 = *reinterpret_cast<const float4*>(SW3p + (c + 1) * 8 + 4);
            float h00 = fmaxf(d[nt][0] + wB0.y, 0.f);
            float h01 = fmaxf(d[nt][1] + wB1.y, 0.f);
            float h10 = fmaxf(d[nt][2] + wB0.y, 0.f);
            float h11 = fmaxf(d[nt][3] + wB1.y, 0.f);
            p0[0] = fmaf(h00, wA0.x, fmaf(h01, wA1.x, p0[0]));
            p0[1] = fmaf(h00, wA0.y, fmaf(h01, wA1.y, p0[1]));
            p0[2] = fmaf(h00, wA0.z, fmaf(h01, wA1.z, p0[2]));
            p0[3] = fmaf(h00, wA0.w, fmaf(h01, wA1.w, p0[3]));
            p0[4] = fmaf(h00, wB0.x, fmaf(h01, wB1.x, p0[4]));
            p1[0] = fmaf(h10, wA0.x, fmaf(h11, wA1.x, p1[0]));
            p1[1] = fmaf(h10, wA0.y, fmaf(h11, wA1.y, p1[1]));
            p1[2] = fmaf(h10, wA0.z, fmaf(h11, wA1.z, p1[2]));
            p1[3] = fmaf(h10, wA0.w, fmaf(h11, wA1.w, p1[3]));
            p1[4] = fmaf(h10, wB0.x, fmaf(h11, wB1.x, p1[4]));
        }
        const bool v0 = (row0 < NC) && (row0 != r);
        const bool v1 = (row1 < NC) && (row1 != r);
        #pragma unroll
        for (int k = 0; k < DE; k++) {
            float a = p0[k], c = p1[k];
            a += __shfl_xor_sync(0xffffffffu, a, 1);
            a += __shfl_xor_sync(0xffffffffu, a, 2);
            c += __shfl_xor_sync(0xffffffffu, c, 1);
            c += __shfl_xor_sync(0xffffffffu, c, 2);
            float e = (v0 ? fmaxf(SB3[k] + a, 0.f) : 0.f)
                    + (v1 ? fmaxf(SB3[k] + c, 0.f) : 0.f);
            e += __shfl_down_sync(0xffffffffu, e, 16);
            e += __shfl_down_sync(0xffffffffu, e, 8);
            e += __shfl_down_sync(0xffffffffu, e, 4);
            if (lane == 0) SRED[wid * DE + k] = e;
        }
        __syncthreads();
        if (tid < DE) {
            float e = 0.f;
            #pragma unroll
            for (int w = 0; w < 12; w++) e += SRED[w * DE + tid];
            SC[rr][PF + tid] = e;     // Ebar -> object-MLP input
        }
        __syncthreads();   // SRED reused next rr; last iter guards DS reuse
    }

    // ================= fused object MLP tail (4 nodes) =================
    // DS smem region is dead now; alias it for SH1/SH2.
    float* SH1 = reinterpret_cast<float*>(dsm);           // [4][128]
    float* SH2 = reinterpret_cast<float*>(dsm) + 512;     // [4][64]

    // fo1: 512 units over 384 threads
    #pragma unroll
    for (int idx = tid; idx < RPB * HID; idx += TPB) {
        const int sub = idx >> 7, i = idx & (HID - 1);
        float a = fo1_b[i];
        #pragma unroll
        for (int m = 0; m < PF + DE; m++)
            a = fmaf(SC[sub][m], fo1_w[m * HID + i], a);
        SH1[sub * HID + i] = fmaxf(a, 0.f);
    }
    __syncthreads();

    // fo2: 256 units (sub, o), 2 accumulators to break the chain
    if (tid < RPB * H2) {
        const int sub = tid >> 6, o = tid & (H2 - 1);
        const float* h1 = SH1 + sub * HID;
        float a0 = fo2_b[o], a1 = 0.f;
        #pragma unroll 8
        for (int m = 0; m < HID; m += 2) {
            a0 = fmaf(h1[m], fo2_w[m * H2 + o], a0);
            a1 = fmaf(h1[m + 1], fo2_w[(m + 1) * H2 + o], a1);
        }
        SH2[sub * H2 + o] = fmaxf(a0 + a1, 0.f);
    }
    __syncthreads();

    // fo3: 24 units
    if (tid < RPB * DOUT) {
        const int sub = tid / DOUT, oo = tid % DOUT;
        const float* h2v = SH2 + sub * H2;
        float a = fo3_b[oo];
        #pragma unroll 8
        for (int m = 0; m < H2; m++)
            a = fmaf(h2v[m], fo3_w[m * DOUT + oo], a);
        g_O[((size_t)b * NC + rbase + sub) * DOUT + oo] = fmaxf(a, 0.f);
    }
}

// ============================================================================
// Kernel B1: fc1 split-K partials. grid (BATCH, 16), 128 threads.
// ============================================================================
__global__ void __launch_bounds__(HID) fc1_kernel(
    const float* __restrict__ fc1_w, const float* __restrict__ fc1_b)
{
    const int b = blockIdx.x, p = blockIdx.y, o = threadIdx.x;
    const int m0 = p * 71;
    const int mend = (m0 + 71 < NC * DOUT) ? m0 + 71 : NC * DOUT;
    const float* Ob = g_O + (size_t)b * NC * DOUT;
    float a0 = (p == 0) ? fc1_b[o] : 0.f, a1 = 0.f;
    int m = m0;
    #pragma unroll 4
    for (; m + 1 < mend; m += 2) {
        a0 = fmaf(Ob[m], fc1_w[m * HID + o], a0);
        a1 = fmaf(Ob[m + 1], fc1_w[(m + 1) * HID + o], a1);
    }
    if (m < mend) a0 = fmaf(Ob[m], fc1_w[m * HID + o], a0);
    g_P1[((size_t)b * 16 + p) * HID + o] = a0 + a1;
}

// ============================================================================
// Kernel B2: finish head. grid BATCH, 128 threads.
// ============================================================================
__global__ void __launch_bounds__(HID) fc2_kernel(
    const float* __restrict__ fc2_w, const float* __restrict__ fc2_b,
    const float* __restrict__ fc3_w, const float* __restrict__ fc3_b,
    float* __restrict__ out)
{
    __shared__ float sh1[HID];
    __shared__ float sp2[2][H2];
    __shared__ float sh2[H2];
    const int b = blockIdx.x, tid = threadIdx.x;

    float a = 0.f;
    #pragma unroll
    for (int p = 0; p < 16; p++)
        a += g_P1[((size_t)b * 16 + p) * HID + tid];
    sh1[tid] = fmaxf(a, 0.f);
    __syncthreads();

    {
        const int o = tid & (H2 - 1), pp = tid >> 6;
        const int m0 = pp * 64;
        float a2 = (pp == 0) ? fc2_b[o] : 0.f;
        #pragma unroll 4
        for (int m = m0; m < m0 + 64; m++)
            a2 = fmaf(sh1[m], fc2_w[m * H2 + o], a2);
        sp2[pp][o] = a2;
    }
    __syncthreads();
    if (tid < H2) sh2[tid] = fmaxf(sp2[0][tid] + sp2[1][tid], 0.f);
    __syncthreads();

    if (tid < NT) {
        float a3 = fc3_b[tid];
        #pragma unroll
        for (int m = 0; m < H2; m++)
            a3 = fmaf(sh2[m], fc3_w[m * NT + tid], a3);
        out[b * NT + tid] = a3;
    }
}

// ============================================================================
// Launch
// ============================================================================
extern "C" void kernel_launch(void* const* d_in, const int* in_sizes, int n_in,
                              void* d_out, int out_size) {
    const float* x     = (const float*)d_in[0];
    const float* fr1_w = (const float*)d_in[1];
    const float* fr1_b = (const float*)d_in[2];
    const float* fr2_w = (const float*)d_in[3];
    const float* fr2_b = (const float*)d_in[4];
    const float* fr3_w = (const float*)d_in[5];
    const float* fr3_b = (const float*)d_in[6];
    const float* fo1_w = (const float*)d_in[7];
    const float* fo1_b = (const float*)d_in[8];
    const float* fo2_w = (const float*)d_in[9];
    const float* fo2_b = (const float*)d_in[10];
    const float* fo3_w = (const float*)d_in[11];
    const float* fo3_b = (const float*)d_in[12];
    const float* fc1_w = (const float*)d_in[13];
    const float* fc1_b = (const float*)d_in[14];
    const float* fc2_w = (const float*)d_in[15];
    const float* fc2_b = (const float*)d_in[16];
    const float* fc3_w = (const float*)d_in[17];
    const float* fc3_b = (const float*)d_in[18];
    float* out = (float*)d_out;

    static bool attr_set = false;
    if (!attr_set) {
        cudaFuncSetAttribute(edge_obj_kernel,
                             cudaFuncAttributeMaxDynamicSharedMemorySize, DYN_SMEM);
        attr_set = true;
    }

    dim3 pgrid(47, BATCH);
    precompute_kernel<<<pgrid, 512>>>(x, fr1_w, fr1_b);
    w2prep_kernel<<<32, 256>>>(fr2_w);

    dim3 egrid(NC / RPB, BATCH);
    edge_obj_kernel<<<egrid, TPB, DYN_SMEM>>>(x, fr2_b, fr3_w, fr3_b,
                                              fo1_w, fo1_b, fo2_w, fo2_b,
                                              fo3_w, fo3_b);

    dim3 fgrid(BATCH, 16);
    fc1_kernel<<<fgrid, HID>>>(fc1_w, fc1_b);
    fc2_kernel<<<BATCH, HID>>>(fc2_w, fc2_b, fc3_w, fc3_b, out);
}

// round 13
// speedup vs baseline: 1.0004x; 1.0004x over previous
#include <cuda_runtime.h>
#include <cuda_bf16.h>
#include <cuda_fp16.h>
#include <cstdint>

// Problem constants
#define NC    188
#define PF    16
#define HID   128
#define H2    64
#define DE    5
#define DOUT  6
#define NT    5
#define BATCH 32
#define TPB   384   // 12 warps; one m16 tile per warp (192 rows)
#define RPB   4     // receivers per block (DS/B staged once; 47*4 = 188)

// DS tile in smem: 192 rows x 136 halves (272 B = 17 uint4 = 68 u32 stride)
#define SROW_U32 68
#define SROW_U4  17
#define DS_BYTES 52224      // 192 * 272
#define B_BYTES  17408      // 64 * 272
#define SM_B     52224
#define DYN_SMEM 69632      // 3 blocks/SM (dynamic)

// Scratch
__device__ float g_O[BATCH * NC * DOUT];
__device__ __align__(16) __half g_DRh[BATCH * NC * HID];  // fp16 DR
__device__ __align__(16) __half g_DSh[BATCH * NC * HID];  // fp16 DS
__device__ __align__(16) __half g_W2h[H2 * 136];
__device__ float g_P1[BATCH * 16 * HID];   // fc1 split-K partials

__device__ __forceinline__ void mma_f16(float* d, const uint32_t* a,
                                        uint32_t b0, uint32_t b1) {
    asm volatile(
        "mma.sync.aligned.m16n8k16.row.col.f32.f16.f16.f32 "
        "{%0,%1,%2,%3}, {%4,%5,%6,%7}, {%8,%9}, {%0,%1,%2,%3};"
        : "+f"(d[0]), "+f"(d[1]), "+f"(d[2]), "+f"(d[3])
        : "r"(a[0]), "r"(a[1]), "r"(a[2]), "r"(a[3]), "r"(b0), "r"(b1));
}

// relu(a + b) on packed f16x2
__device__ __forceinline__ uint32_t h2_relu_add(uint32_t a, uint32_t b) {
    uint32_t r;
    asm("{\n\tadd.f16x2 %0, %1, %2;\n\tmax.f16x2 %0, %0, %3;\n\t}"
        : "=r"(r) : "r"(a), "r"(b), "r"(0u));
    return r;
}

// ============================================================================
// Kernel P: per-node layer-1 half-dots -> fp16 (4 nodes/block, 512 thr),
// plus W2 prep on the extra grid column (bx == 47).
// ============================================================================
__global__ void __launch_bounds__(512) precompute_kernel(
    const float* __restrict__ x,
    const float* __restrict__ fr1_w, const float* __restrict__ fr1_b,
    const float* __restrict__ fr2_w)
{
    if (blockIdx.x == 47) {
        // W2^T -> fp16 image [64][136]; only one block row does the work
        if (blockIdx.y == 0) {
            for (int idx = threadIdx.x; idx < HID * H2; idx += 512) {
                int o = idx >> 7, k = idx & 127;
                g_W2h[o * 136 + k] = __float2half_rn(fr2_w[k * H2 + o]);
            }
        }
        return;
    }
    __shared__ float SX[4][PF];
    const int sub = threadIdx.x >> 7;
    const int i = threadIdx.x & (HID - 1);
    const int n = blockIdx.x * 4 + sub;          // 47*4 = 188
    const int b = blockIdx.y;
    if (i < PF) SX[sub][i] = x[((size_t)b * NC + n) * PF + i];
    __syncthreads();
    float dr = fr1_b[i], ds = 0.f;
    #pragma unroll
    for (int m = 0; m < PF; m++) {
        float xm = SX[sub][m];
        dr = fmaf(xm, fr1_w[m * HID + i], dr);
        ds = fmaf(xm, fr1_w[(PF + m) * HID + i], ds);
    }
    g_DRh[((size_t)b * NC + n) * HID + i] = __float2half_rn(dr);
    g_DSh[((size_t)b * NC + n) * HID + i] = __float2half_rn(ds);
}

// ============================================================================
// Kernel A: one block per (4 receivers, batch). fp16 mma.sync GEMM for 4
// receivers + fused object MLP tail (DS smem region reused for SH1/SH2).
// ============================================================================
__global__ void __launch_bounds__(TPB, 3) edge_obj_kernel(
    const float* __restrict__ x,
    const float* __restrict__ fr2_b,
    const float* __restrict__ fr3_w, const float* __restrict__ fr3_b,
    const float* __restrict__ fo1_w, const float* __restrict__ fo1_b,
    const float* __restrict__ fo2_w, const float* __restrict__ fo2_b,
    const float* __restrict__ fo3_w, const float* __restrict__ fo3_b)
{
    extern __shared__ __align__(16) unsigned char dsm[];
    __shared__ __align__(16) float SW3p[H2 * 8];   // per o: w3[0..4], b2, 0, 0
    __shared__ __align__(8) uint32_t SDR16[RPB][64];
    __shared__ float SC[RPB][24];                  // [x(16), Ebar(5)]
    __shared__ float SB3[8];
    __shared__ float SRED[12 * DE];

    const uint32_t* DS32 = reinterpret_cast<const uint32_t*>(dsm);
    const uint32_t* B32 = reinterpret_cast<const uint32_t*>(dsm + SM_B);

    const int rbase = blockIdx.x * RPB, b = blockIdx.y;
    const int tid = threadIdx.x, wid = tid >> 5, lane = tid & 31;
    const int gid = lane >> 2, tig = lane & 3;

    // ---- stage: DS tile (raw copy), B, DR x RPB, W3, x ----
    {
        const uint4* src = reinterpret_cast<const uint4*>(
            g_DSh + (size_t)b * NC * HID);
        uint4* dst = reinterpret_cast<uint4*>(dsm);
        #pragma unroll 4
        for (int idx = tid; idx < NC * 16; idx += TPB) {   // 3008 uint4
            int row = idx >> 4, col = idx & 15;
            dst[row * SROW_U4 + col] = src[idx];
        }
        if (tid < 68) {   // pad rows 188..191 = -inf so relu -> 0
            uint4 ninf = {0xFC00FC00u, 0xFC00FC00u, 0xFC00FC00u, 0xFC00FC00u};
            int row = NC + tid / SROW_U4, col = tid % SROW_U4;
            dst[row * SROW_U4 + col] = ninf;
        }
    }
    {
        const uint4* sh = reinterpret_cast<const uint4*>(g_W2h);
        uint4* dh = reinterpret_cast<uint4*>(dsm + SM_B);
        #pragma unroll 2
        for (int idx = tid; idx < B_BYTES / 16; idx += TPB) dh[idx] = sh[idx];
    }
    if (tid < RPB * 64) {
        int rr = tid >> 6, w = tid & 63;
        SDR16[rr][w] = reinterpret_cast<const uint32_t*>(
            g_DRh + ((size_t)b * NC + rbase + rr) * HID)[w];
    }
    for (int idx = tid; idx < H2 * 8; idx += TPB) {
        int o = idx >> 3, k = idx & 7;
        SW3p[idx] = (k < 5) ? fr3_w[o * DE + k] : (k == 5 ? fr2_b[o] : 0.f);
    }
    if (tid < DE) SB3[tid] = fr3_b[tid];
    if (tid >= 32 && tid < 32 + RPB * PF) {
        int t = tid - 32, sub = t >> 4, m = t & 15;
        SC[sub][m] = x[((size_t)b * NC + rbase + sub) * PF + m];
    }
    __syncthreads();

    const int abase0 = (wid * 16 + gid) * SROW_U32;
    const int row0 = wid * 16 + gid, row1 = row0 + 8;

    #pragma unroll 1
    for (int rr = 0; rr < RPB; rr++) {
        const int r = rbase + rr;

        // ---- GEMM: warp wid owns m16 tile rows [16*wid, 16*wid+16) ----
        float d[8][4];
        #pragma unroll
        for (int nt = 0; nt < 8; nt++)
            #pragma unroll
            for (int e = 0; e < 4; e++) d[nt][e] = 0.f;

        #pragma unroll
        for (int kt = 0; kt < 8; kt++) {
            const int kb = kt * 8 + tig;
            const uint32_t dr0 = SDR16[rr][kb], dr1 = SDR16[rr][kb + 4];
            uint32_t af[4];
            af[0] = h2_relu_add(DS32[abase0 + kb], dr0);
            af[1] = h2_relu_add(DS32[abase0 + 8 * SROW_U32 + kb], dr0);
            af[2] = h2_relu_add(DS32[abase0 + kb + 4], dr1);
            af[3] = h2_relu_add(DS32[abase0 + 8 * SROW_U32 + kb + 4], dr1);
            #pragma unroll
            for (int nt = 0; nt < 8; nt++) {
                const int bi = (nt * 8 + gid) * SROW_U32 + kb;
                mma_f16(d[nt], af, B32[bi], B32[bi + 4]);
            }
        }

        // ---- fragment-direct epilogue: layer 3 partials ----
        float p0[DE] = {0.f, 0.f, 0.f, 0.f, 0.f};
        float p1[DE] = {0.f, 0.f, 0.f, 0.f, 0.f};
        #pragma unroll
        for (int nt = 0; nt < 8; nt++) {
            const int c = nt * 8 + tig * 2;
            float4 wA0 = *reinterpret_cast<const float4*>(SW3p + c * 8);
            float4 wB0 = *reinterpret_cast<const float4*>(SW3p + c * 8 + 4);
            float4 wA1 = *reinterpret_cast<const float4*>(SW3p + (c + 1) * 8);
            float4 wB1 = *reinterpret_cast<const float4*>(SW3p + (c + 1) * 8 + 4);
            float h00 = fmaxf(d[nt][0] + wB0.y, 0.f);
            float h01 = fmaxf(d[nt][1] + wB1.y, 0.f);
            float h10 = fmaxf(d[nt][2] + wB0.y, 0.f);
            float h11 = fmaxf(d[nt][3] + wB1.y, 0.f);
            p0[0] = fmaf(h00, wA0.x, fmaf(h01, wA1.x, p0[0]));
            p0[1] = fmaf(h00, wA0.y, fmaf(h01, wA1.y, p0[1]));
            p0[2] = fmaf(h00, wA0.z, fmaf(h01, wA1.z, p0[2]));
            p0[3] = fmaf(h00, wA0.w, fmaf(h01, wA1.w, p0[3]));
            p0[4] = fmaf(h00, wB0.x, fmaf(h01, wB1.x, p0[4]));
            p1[0] = fmaf(h10, wA0.x, fmaf(h11, wA1.x, p1[0]));
            p1[1] = fmaf(h10, wA0.y, fmaf(h11, wA1.y, p1[1]));
            p1[2] = fmaf(h10, wA0.z, fmaf(h11, wA1.z, p1[2]));
            p1[3] = fmaf(h10, wA0.w, fmaf(h11, wA1.w, p1[3]));
            p1[4] = fmaf(h10, wB0.x, fmaf(h11, wB1.x, p1[4]));
        }
        const bool v0 = (row0 < NC) && (row0 != r);
        const bool v1 = (row1 < NC) && (row1 != r);
        #pragma unroll
        for (int k = 0; k < DE; k++) {
            float a = p0[k], c = p1[k];
            a += __shfl_xor_sync(0xffffffffu, a, 1);
            a += __shfl_xor_sync(0xffffffffu, a, 2);
            c += __shfl_xor_sync(0xffffffffu, c, 1);
            c += __shfl_xor_sync(0xffffffffu, c, 2);
            float e = (v0 ? fmaxf(SB3[k] + a, 0.f) : 0.f)
                    + (v1 ? fmaxf(SB3[k] + c, 0.f) : 0.f);
            e += __shfl_down_sync(0xffffffffu, e, 16);
            e += __shfl_down_sync(0xffffffffu, e, 8);
            e += __shfl_down_sync(0xffffffffu, e, 4);
            if (lane == 0) SRED[wid * DE + k] = e;
        }
        __syncthreads();
        if (tid < DE) {
            float e = 0.f;
            #pragma unroll
            for (int w = 0; w < 12; w++) e += SRED[w * DE + tid];
            SC[rr][PF + tid] = e;     // Ebar -> object-MLP input
        }
        __syncthreads();   // SRED reused next rr; last iter guards DS reuse
    }

    // ================= fused object MLP tail (4 nodes) =================
    float* SH1 = reinterpret_cast<float*>(dsm);           // [4][128]
    float* SH2 = reinterpret_cast<float*>(dsm) + 512;     // [4][64]

    // fo1: 512 units over 384 threads
    #pragma unroll
    for (int idx = tid; idx < RPB * HID; idx += TPB) {
        const int sub = idx >> 7, i = idx & (HID - 1);
        float a = fo1_b[i];
        #pragma unroll
        for (int m = 0; m < PF + DE; m++)
            a = fmaf(SC[sub][m], fo1_w[m * HID + i], a);
        SH1[sub * HID + i] = fmaxf(a, 0.f);
    }
    __syncthreads();

    // fo2: 256 units (sub, o), 2 accumulators
    if (tid < RPB * H2) {
        const int sub = tid >> 6, o = tid & (H2 - 1);
        const float* h1 = SH1 + sub * HID;
        float a0 = fo2_b[o], a1 = 0.f;
        #pragma unroll 8
        for (int m = 0; m < HID; m += 2) {
            a0 = fmaf(h1[m], fo2_w[m * H2 + o], a0);
            a1 = fmaf(h1[m + 1], fo2_w[(m + 1) * H2 + o], a1);
        }
        SH2[sub * H2 + o] = fmaxf(a0 + a1, 0.f);
    }
    __syncthreads();

    // fo3: 24 units
    if (tid < RPB * DOUT) {
        const int sub = tid / DOUT, oo = tid % DOUT;
        const float* h2v = SH2 + sub * H2;
        float a = fo3_b[oo];
        #pragma unroll 8
        for (int m = 0; m < H2; m++)
            a = fmaf(h2v[m], fo3_w[m * DOUT + oo], a);
        g_O[((size_t)b * NC + rbase + sub) * DOUT + oo] = fmaxf(a, 0.f);
    }
}

// ============================================================================
// Kernel B1: fc1 split-K partials. grid (BATCH, 16), 512 threads.
// Inner 4-way m-split cuts serial chain 71 -> 18; smem tree reduce.
// ============================================================================
__global__ void __launch_bounds__(512) fc1_kernel(
    const float* __restrict__ fc1_w, const float* __restrict__ fc1_b)
{
    __shared__ float sp[4][HID];
    const int b = blockIdx.x, p = blockIdx.y;
    const int o = threadIdx.x & (HID - 1), q = threadIdx.x >> 7;  // q 0..3
    const int base = p * 71;
    const int len = (base + 71 <= NC * DOUT) ? 71 : (NC * DOUT - base);
    const int m0 = base + ((q * len) >> 2);
    const int m1 = base + (((q + 1) * len) >> 2);
    const float* Ob = g_O + (size_t)b * NC * DOUT;
    float a = (p == 0 && q == 0) ? fc1_b[o] : 0.f;
    #pragma unroll 3
    for (int m = m0; m < m1; m++)
        a = fmaf(Ob[m], fc1_w[m * HID + o], a);
    sp[q][o] = a;
    __syncthreads();
    if (threadIdx.x < HID)
        g_P1[((size_t)b * 16 + p) * HID + threadIdx.x] =
            (sp[0][threadIdx.x] + sp[1][threadIdx.x]) +
            (sp[2][threadIdx.x] + sp[3][threadIdx.x]);
}

// ============================================================================
// Kernel B2: finish head. grid BATCH, 128 threads.
// ============================================================================
__global__ void __launch_bounds__(HID) fc2_kernel(
    const float* __restrict__ fc2_w, const float* __restrict__ fc2_b,
    const float* __restrict__ fc3_w, const float* __restrict__ fc3_b,
    float* __restrict__ out)
{
    __shared__ float sh1[HID];
    __shared__ float sp2[2][H2];
    __shared__ float sh2[H2];
    const int b = blockIdx.x, tid = threadIdx.x;

    float a = 0.f;
    #pragma unroll
    for (int p = 0; p < 16; p++)
        a += g_P1[((size_t)b * 16 + p) * HID + tid];
    sh1[tid] = fmaxf(a, 0.f);
    __syncthreads();

    {
        const int o = tid & (H2 - 1), pp = tid >> 6;
        const int m0 = pp * 64;
        float a2 = (pp == 0) ? fc2_b[o] : 0.f;
        #pragma unroll 4
        for (int m = m0; m < m0 + 64; m++)
            a2 = fmaf(sh1[m], fc2_w[m * H2 + o], a2);
        sp2[pp][o] = a2;
    }
    __syncthreads();
    if (tid < H2) sh2[tid] = fmaxf(sp2[0][tid] + sp2[1][tid], 0.f);
    __syncthreads();

    if (tid < NT) {
        float a3 = fc3_b[tid];
        #pragma unroll
        for (int m = 0; m < H2; m++)
            a3 = fmaf(sh2[m], fc3_w[m * NT + tid], a3);
        out[b * NT + tid] = a3;
    }
}

// ============================================================================
// Launch
// ============================================================================
extern "C" void kernel_launch(void* const* d_in, const int* in_sizes, int n_in,
                              void* d_out, int out_size) {
    const float* x     = (const float*)d_in[0];
    const float* fr1_w = (const float*)d_in[1];
    const float* fr1_b = (const float*)d_in[2];
    const float* fr2_w = (const float*)d_in[3];
    const float* fr2_b = (const float*)d_in[4];
    const float* fr3_w = (const float*)d_in[5];
    const float* fr3_b = (const float*)d_in[6];
    const float* fo1_w = (const float*)d_in[7];
    const float* fo1_b = (const float*)d_in[8];
    const float* fo2_w = (const float*)d_in[9];
    const float* fo2_b = (const float*)d_in[10];
    const float* fo3_w = (const float*)d_in[11];
    const float* fo3_b = (const float*)d_in[12];
    const float* fc1_w = (const float*)d_in[13];
    const float* fc1_b = (const float*)d_in[14];
    const float* fc2_w = (const float*)d_in[15];
    const float* fc2_b = (const float*)d_in[16];
    const float* fc3_w = (const float*)d_in[17];
    const float* fc3_b = (const float*)d_in[18];
    float* out = (float*)d_out;

    static bool attr_set = false;
    if (!attr_set) {
        cudaFuncSetAttribute(edge_obj_kernel,
                             cudaFuncAttributeMaxDynamicSharedMemorySize, DYN_SMEM);
        attr_set = true;
    }

    dim3 pgrid(48, BATCH);   // col 47 = W2 prep
    precompute_kernel<<<pgrid, 512>>>(x, fr1_w, fr1_b, fr2_w);

    dim3 egrid(NC / RPB, BATCH);
    edge_obj_kernel<<<egrid, TPB, DYN_SMEM>>>(x, fr2_b, fr3_w, fr3_b,
                                              fo1_w, fo1_b, fo2_w, fo2_b,
                                              fo3_w, fo3_b);

    dim3 fgrid(BATCH, 16);
    fc1_kernel<<<fgrid, 512>>>(fc1_w, fc1_b);
    fc2_kernel<<<BATCH, HID>>>(fc2_w, fc2_b, fc3_w, fc3_b, out);
}

// round 14
// speedup vs baseline: 1.0411x; 1.0406x over previous
#include <cuda_runtime.h>
#include <cuda_bf16.h>
#include <cuda_fp16.h>
#include <cstdint>

// Problem constants
#define NC    188
#define PF    16
#define HID   128
#define H2    64
#define DE    5
#define DOUT  6
#define NT    5
#define BATCH 32
#define TPB   384   // 12 warps; one m16 tile per warp (192 rows)
#define RPB   4     // receivers per block (DS/B staged once; 47*4 = 188)

// DS tile in smem: 192 rows x 136 halves (272 B = 17 uint4 = 68 u32 stride)
#define SROW_U32 68
#define SROW_U4  17
#define DS_BYTES 52224      // 192 * 272
#define B_BYTES  17408      // 64 * 272
#define SM_B     52224
#define DYN_SMEM 69632      // 3 blocks/SM (dynamic)

// Scratch
__device__ float g_O[BATCH * NC * DOUT];
__device__ __align__(16) __half g_DRh[BATCH * NC * HID];  // fp16 DR
__device__ __align__(16) __half g_DSh[BATCH * NC * HID];  // fp16 DS
__device__ __align__(16) __half g_W2h[H2 * 136];
__device__ float g_P1[BATCH * 16 * HID];   // fc1 split-K partials

__device__ __forceinline__ void mma_f16(float* d, const uint32_t* a,
                                        uint32_t b0, uint32_t b1) {
    asm volatile(
        "mma.sync.aligned.m16n8k16.row.col.f32.f16.f16.f32 "
        "{%0,%1,%2,%3}, {%4,%5,%6,%7}, {%8,%9}, {%0,%1,%2,%3};"
        : "+f"(d[0]), "+f"(d[1]), "+f"(d[2]), "+f"(d[3])
        : "r"(a[0]), "r"(a[1]), "r"(a[2]), "r"(a[3]), "r"(b0), "r"(b1));
}

// relu(a + b) on packed f16x2
__device__ __forceinline__ uint32_t h2_relu_add(uint32_t a, uint32_t b) {
    uint32_t r;
    asm("{\n\tadd.f16x2 %0, %1, %2;\n\tmax.f16x2 %0, %0, %3;\n\t}"
        : "=r"(r) : "r"(a), "r"(b), "r"(0u));
    return r;
}

// ============================================================================
// Kernel P: per-node layer-1 half-dots -> fp16 (4 nodes/block, 512 thr),
// plus W2 prep on the extra grid column (bx == 47).
// ============================================================================
__global__ void __launch_bounds__(512) precompute_kernel(
    const float* __restrict__ x,
    const float* __restrict__ fr1_w, const float* __restrict__ fr1_b,
    const float* __restrict__ fr2_w)
{
    if (blockIdx.x == 47) {
        if (blockIdx.y == 0) {
            for (int idx = threadIdx.x; idx < HID * H2; idx += 512) {
                int o = idx >> 7, k = idx & 127;
                g_W2h[o * 136 + k] = __float2half_rn(fr2_w[k * H2 + o]);
            }
        }
        return;
    }
    __shared__ float SX[4][PF];
    const int sub = threadIdx.x >> 7;
    const int i = threadIdx.x & (HID - 1);
    const int n = blockIdx.x * 4 + sub;          // 47*4 = 188
    const int b = blockIdx.y;
    if (i < PF) SX[sub][i] = x[((size_t)b * NC + n) * PF + i];
    __syncthreads();
    float dr = fr1_b[i], ds = 0.f;
    #pragma unroll
    for (int m = 0; m < PF; m++) {
        float xm = SX[sub][m];
        dr = fmaf(xm, fr1_w[m * HID + i], dr);
        ds = fmaf(xm, fr1_w[(PF + m) * HID + i], ds);
    }
    g_DRh[((size_t)b * NC + n) * HID + i] = __float2half_rn(dr);
    g_DSh[((size_t)b * NC + n) * HID + i] = __float2half_rn(ds);
}

// ============================================================================
// Kernel A: one block per (4 receivers, batch). fp16 mma.sync GEMM for 4
// receivers (sync-free inner loop) + fused object MLP tail.
// ============================================================================
__global__ void __launch_bounds__(TPB, 3) edge_obj_kernel(
    const float* __restrict__ x,
    const float* __restrict__ fr2_b,
    const float* __restrict__ fr3_w, const float* __restrict__ fr3_b,
    const float* __restrict__ fo1_w, const float* __restrict__ fo1_b,
    const float* __restrict__ fo2_w, const float* __restrict__ fo2_b,
    const float* __restrict__ fo3_w, const float* __restrict__ fo3_b)
{
    extern __shared__ __align__(16) unsigned char dsm[];
    __shared__ __align__(16) float SW3p[H2 * 8];   // per o: w3[0..4], b2, 0, 0
    __shared__ __align__(8) uint32_t SDR16[RPB][64];
    __shared__ float SC[RPB][24];                  // [x(16), Ebar(5)]
    __shared__ float SB3[8];
    __shared__ float SRED[RPB][12][DE];            // per-receiver partials

    const uint32_t* DS32 = reinterpret_cast<const uint32_t*>(dsm);
    const uint32_t* B32 = reinterpret_cast<const uint32_t*>(dsm + SM_B);

    const int rbase = blockIdx.x * RPB, b = blockIdx.y;
    const int tid = threadIdx.x, wid = tid >> 5, lane = tid & 31;
    const int gid = lane >> 2, tig = lane & 3;

    // ---- stage: DS tile (raw copy), B, DR x RPB, W3, x ----
    {
        const uint4* src = reinterpret_cast<const uint4*>(
            g_DSh + (size_t)b * NC * HID);
        uint4* dst = reinterpret_cast<uint4*>(dsm);
        #pragma unroll 4
        for (int idx = tid; idx < NC * 16; idx += TPB) {   // 3008 uint4
            int row = idx >> 4, col = idx & 15;
            dst[row * SROW_U4 + col] = src[idx];
        }
        if (tid < 68) {   // pad rows 188..191 = -inf so relu -> 0
            uint4 ninf = {0xFC00FC00u, 0xFC00FC00u, 0xFC00FC00u, 0xFC00FC00u};
            int row = NC + tid / SROW_U4, col = tid % SROW_U4;
            dst[row * SROW_U4 + col] = ninf;
        }
    }
    {
        const uint4* sh = reinterpret_cast<const uint4*>(g_W2h);
        uint4* dh = reinterpret_cast<uint4*>(dsm + SM_B);
        #pragma unroll 2
        for (int idx = tid; idx < B_BYTES / 16; idx += TPB) dh[idx] = sh[idx];
    }
    if (tid < RPB * 64) {
        int rr = tid >> 6, w = tid & 63;
        SDR16[rr][w] = reinterpret_cast<const uint32_t*>(
            g_DRh + ((size_t)b * NC + rbase + rr) * HID)[w];
    }
    for (int idx = tid; idx < H2 * 8; idx += TPB) {
        int o = idx >> 3, k = idx & 7;
        SW3p[idx] = (k < 5) ? fr3_w[o * DE + k] : (k == 5 ? fr2_b[o] : 0.f);
    }
    if (tid < DE) SB3[tid] = fr3_b[tid];
    if (tid >= 32 && tid < 32 + RPB * PF) {
        int t = tid - 32, sub = t >> 4, m = t & 15;
        SC[sub][m] = x[((size_t)b * NC + rbase + sub) * PF + m];
    }
    __syncthreads();

    const int abase0 = (wid * 16 + gid) * SROW_U32;
    const int row0 = wid * 16 + gid, row1 = row0 + 8;

    // ---- sync-free 4-receiver loop ----
    #pragma unroll 1
    for (int rr = 0; rr < RPB; rr++) {
        const int r = rbase + rr;

        float d[8][4];
        #pragma unroll
        for (int nt = 0; nt < 8; nt++)
            #pragma unroll
            for (int e = 0; e < 4; e++) d[nt][e] = 0.f;

        #pragma unroll
        for (int kt = 0; kt < 8; kt++) {
            const int kb = kt * 8 + tig;
            const uint32_t dr0 = SDR16[rr][kb], dr1 = SDR16[rr][kb + 4];
            uint32_t af[4];
            af[0] = h2_relu_add(DS32[abase0 + kb], dr0);
            af[1] = h2_relu_add(DS32[abase0 + 8 * SROW_U32 + kb], dr0);
            af[2] = h2_relu_add(DS32[abase0 + kb + 4], dr1);
            af[3] = h2_relu_add(DS32[abase0 + 8 * SROW_U32 + kb + 4], dr1);
            #pragma unroll
            for (int nt = 0; nt < 8; nt++) {
                const int bi = (nt * 8 + gid) * SROW_U32 + kb;
                mma_f16(d[nt], af, B32[bi], B32[bi + 4]);
            }
        }

        // ---- fragment-direct epilogue: layer 3 partials ----
        float p0[DE] = {0.f, 0.f, 0.f, 0.f, 0.f};
        float p1[DE] = {0.f, 0.f, 0.f, 0.f, 0.f};
        #pragma unroll
        for (int nt = 0; nt < 8; nt++) {
            const int c = nt * 8 + tig * 2;
            float4 wA0 = *reinterpret_cast<const float4*>(SW3p + c * 8);
            float4 wB0 = *reinterpret_cast<const float4*>(SW3p + c * 8 + 4);
            float4 wA1 = *reinterpret_cast<const float4*>(SW3p + (c + 1) * 8);
            float4 wB1 = *reinterpret_cast<const float4*>(SW3p + (c + 1) * 8 + 4);
            float h00 = fmaxf(d[nt][0] + wB0.y, 0.f);
            float h01 = fmaxf(d[nt][1] + wB1.y, 0.f);
            float h10 = fmaxf(d[nt][2] + wB0.y, 0.f);
            float h11 = fmaxf(d[nt][3] + wB1.y, 0.f);
            p0[0] = fmaf(h00, wA0.x, fmaf(h01, wA1.x, p0[0]));
            p0[1] = fmaf(h00, wA0.y, fmaf(h01, wA1.y, p0[1]));
            p0[2] = fmaf(h00, wA0.z, fmaf(h01, wA1.z, p0[2]));
            p0[3] = fmaf(h00, wA0.w, fmaf(h01, wA1.w, p0[3]));
            p0[4] = fmaf(h00, wB0.x, fmaf(h01, wB1.x, p0[4]));
            p1[0] = fmaf(h10, wA0.x, fmaf(h11, wA1.x, p1[0]));
            p1[1] = fmaf(h10, wA0.y, fmaf(h11, wA1.y, p1[1]));
            p1[2] = fmaf(h10, wA0.z, fmaf(h11, wA1.z, p1[2]));
            p1[3] = fmaf(h10, wA0.w, fmaf(h11, wA1.w, p1[3]));
            p1[4] = fmaf(h10, wB0.x, fmaf(h11, wB1.x, p1[4]));
        }
        const bool v0 = (row0 < NC) && (row0 != r);
        const bool v1 = (row1 < NC) && (row1 != r);
        #pragma unroll
        for (int k = 0; k < DE; k++) {
            float a = p0[k], c = p1[k];
            a += __shfl_xor_sync(0xffffffffu, a, 1);
            a += __shfl_xor_sync(0xffffffffu, a, 2);
            c += __shfl_xor_sync(0xffffffffu, c, 1);
            c += __shfl_xor_sync(0xffffffffu, c, 2);
            float e = (v0 ? fmaxf(SB3[k] + a, 0.f) : 0.f)
                    + (v1 ? fmaxf(SB3[k] + c, 0.f) : 0.f);
            e += __shfl_down_sync(0xffffffffu, e, 16);
            e += __shfl_down_sync(0xffffffffu, e, 8);
            e += __shfl_down_sync(0xffffffffu, e, 4);
            if (lane == 0) SRED[rr][wid][k] = e;
        }
    }
    __syncthreads();   // all warps done: SRED complete, DS reads finished

    if (tid < RPB * DE) {
        const int rr = tid / DE, k = tid % DE;
        float e = 0.f;
        #pragma unroll
        for (int w = 0; w < 12; w++) e += SRED[rr][w][k];
        SC[rr][PF + k] = e;
    }
    __syncthreads();

    // ================= fused object MLP tail (4 nodes) =================
    float* SH1 = reinterpret_cast<float*>(dsm);           // [4][128]
    float* SH2 = reinterpret_cast<float*>(dsm) + 512;     // [4][64]

    // fo1: 512 units over 384 threads
    #pragma unroll
    for (int idx = tid; idx < RPB * HID; idx += TPB) {
        const int sub = idx >> 7, i = idx & (HID - 1);
        float a = fo1_b[i];
        #pragma unroll
        for (int m = 0; m < PF + DE; m++)
            a = fmaf(SC[sub][m], fo1_w[m * HID + i], a);
        SH1[sub * HID + i] = fmaxf(a, 0.f);
    }
    __syncthreads();

    // fo2: 256 units (sub, o), 2 accumulators
    if (tid < RPB * H2) {
        const int sub = tid >> 6, o = tid & (H2 - 1);
        const float* h1 = SH1 + sub * HID;
        float a0 = fo2_b[o], a1 = 0.f;
        #pragma unroll 8
        for (int m = 0; m < HID; m += 2) {
            a0 = fmaf(h1[m], fo2_w[m * H2 + o], a0);
            a1 = fmaf(h1[m + 1], fo2_w[(m + 1) * H2 + o], a1);
        }
        SH2[sub * H2 + o] = fmaxf(a0 + a1, 0.f);
    }
    __syncthreads();

    // fo3: 24 units
    if (tid < RPB * DOUT) {
        const int sub = tid / DOUT, oo = tid % DOUT;
        const float* h2v = SH2 + sub * H2;
        float a = fo3_b[oo];
        #pragma unroll 8
        for (int m = 0; m < H2; m++)
            a = fmaf(h2v[m], fo3_w[m * DOUT + oo], a);
        g_O[((size_t)b * NC + rbase + sub) * DOUT + oo] = fmaxf(a, 0.f);
    }
}

// ============================================================================
// Kernel B1: fc1 split-K partials. grid (BATCH, 16), 512 threads.
// ============================================================================
__global__ void __launch_bounds__(512) fc1_kernel(
    const float* __restrict__ fc1_w, const float* __restrict__ fc1_b)
{
    __shared__ float sp[4][HID];
    const int b = blockIdx.x, p = blockIdx.y;
    const int o = threadIdx.x & (HID - 1), q = threadIdx.x >> 7;  // q 0..3
    const int base = p * 71;
    const int len = (base + 71 <= NC * DOUT) ? 71 : (NC * DOUT - base);
    const int m0 = base + ((q * len) >> 2);
    const int m1 = base + (((q + 1) * len) >> 2);
    const float* Ob = g_O + (size_t)b * NC * DOUT;
    float a = (p == 0 && q == 0) ? fc1_b[o] : 0.f;
    #pragma unroll 3
    for (int m = m0; m < m1; m++)
        a = fmaf(Ob[m], fc1_w[m * HID + o], a);
    sp[q][o] = a;
    __syncthreads();
    if (threadIdx.x < HID)
        g_P1[((size_t)b * 16 + p) * HID + threadIdx.x] =
            (sp[0][threadIdx.x] + sp[1][threadIdx.x]) +
            (sp[2][threadIdx.x] + sp[3][threadIdx.x]);
}

// ============================================================================
// Kernel B2: finish head. grid BATCH, 512 threads, fully parallel chains.
// ============================================================================
__global__ void __launch_bounds__(512) fc2_kernel(
    const float* __restrict__ fc2_w, const float* __restrict__ fc2_b,
    const float* __restrict__ fc3_w, const float* __restrict__ fc3_b,
    float* __restrict__ out)
{
    __shared__ float sp1[4][HID];
    __shared__ float sh1[HID];
    __shared__ float sp2[8][H2];
    __shared__ float sh2[H2];
    __shared__ float sp3[8][NT];
    const int b = blockIdx.x, tid = threadIdx.x;

    // reduce 16 fc1 partials: (o, q) each sums 4
    {
        const int o = tid & (HID - 1), q = tid >> 7;   // q 0..3
        const float* P = g_P1 + (size_t)b * 16 * HID;
        float a = P[(q * 4 + 0) * HID + o] + P[(q * 4 + 1) * HID + o]
                + P[(q * 4 + 2) * HID + o] + P[(q * 4 + 3) * HID + o];
        sp1[q][o] = a;
    }
    __syncthreads();
    if (tid < HID)
        sh1[tid] = fmaxf((sp1[0][tid] + sp1[1][tid]) +
                         (sp1[2][tid] + sp1[3][tid]), 0.f);
    __syncthreads();

    // fc2: 128 -> 64, 8-way split over K (16 each)
    {
        const int o = tid & (H2 - 1), pp = tid >> 6;   // pp 0..7
        const int m0 = pp * 16;
        float a = (pp == 0) ? fc2_b[o] : 0.f;
        #pragma unroll
        for (int m = m0; m < m0 + 16; m++)
            a = fmaf(sh1[m], fc2_w[m * H2 + o], a);
        sp2[pp][o] = a;
    }
    __syncthreads();
    if (tid < H2) {
        float h = 0.f;
        #pragma unroll
        for (int p = 0; p < 8; p++) h += sp2[p][tid];
        sh2[tid] = fmaxf(h, 0.f);
    }
    __syncthreads();

    // fc3: 64 -> 5, 8-way split over K
    if (tid < NT * 8) {
        const int oo = tid % NT, q = tid / NT;         // q 0..7
        const int m0 = q * 8;
        float a = (q == 0) ? fc3_b[oo] : 0.f;
        #pragma unroll
        for (int m = m0; m < m0 + 8; m++)
            a = fmaf(sh2[m], fc3_w[m * NT + oo], a);
        sp3[q][oo] = a;
    }
    __syncthreads();
    if (tid < NT) {
        float a = 0.f;
        #pragma unroll
        for (int q = 0; q < 8; q++) a += sp3[q][tid];
        out[b * NT + tid] = a;
    }
}

// ============================================================================
// Launch
// ============================================================================
extern "C" void kernel_launch(void* const* d_in, const int* in_sizes, int n_in,
                              void* d_out, int out_size) {
    const float* x     = (const float*)d_in[0];
    const float* fr1_w = (const float*)d_in[1];
    const float* fr1_b = (const float*)d_in[2];
    const float* fr2_w = (const float*)d_in[3];
    const float* fr2_b = (const float*)d_in[4];
    const float* fr3_w = (const float*)d_in[5];
    const float* fr3_b = (const float*)d_in[6];
    const float* fo1_w = (const float*)d_in[7];
    const float* fo1_b = (const float*)d_in[8];
    const float* fo2_w = (const float*)d_in[9];
    const float* fo2_b = (const float*)d_in[10];
    const float* fo3_w = (const float*)d_in[11];
    const float* fo3_b = (const float*)d_in[12];
    const float* fc1_w = (const float*)d_in[13];
    const float* fc1_b = (const float*)d_in[14];
    const float* fc2_w = (const float*)d_in[15];
    const float* fc2_b = (const float*)d_in[16];
    const float* fc3_w = (const float*)d_in[17];
    const float* fc3_b = (const float*)d_in[18];
    float* out = (float*)d_out;

    static bool attr_set = false;
    if (!attr_set) {
        cudaFuncSetAttribute(edge_obj_kernel,
                             cudaFuncAttributeMaxDynamicSharedMemorySize, DYN_SMEM);
        attr_set = true;
    }

    dim3 pgrid(48, BATCH);   // col 47 = W2 prep
    precompute_kernel<<<pgrid, 512>>>(x, fr1_w, fr1_b, fr2_w);

    dim3 egrid(NC / RPB, BATCH);
    edge_obj_kernel<<<egrid, TPB, DYN_SMEM>>>(x, fr2_b, fr3_w, fr3_b,
                                              fo1_w, fo1_b, fo2_w, fo2_b,
                                              fo3_w, fo3_b);

    dim3 fgrid(BATCH, 16);
    fc1_kernel<<<fgrid, 512>>>(fc1_w, fc1_b);
    fc2_kernel<<<BATCH, 512>>>(fc2_w, fc2_b, fc3_w, fc3_b, out);
}